// round 1
// baseline (speedup 1.0000x reference)
#include <cuda_runtime.h>
#include <cstdint>

#define N_EMB   8192
#define DDIM    256
#define BB      32
#define HH      32
#define WW      32
#define HW      1024            // H*W
#define NQ      32768           // B*H*W
#define ZQ_ELEMS 8388608        // B*D*H*W
#define NSPLIT  4
#define KSPLIT  (N_EMB / NSPLIT)   // 2048
#define QT      128             // queries per CTA
#define ET      128             // embedding tile
#define DK      16              // d-chunk
#define ES_STRIDE 132           // padded Es row (floats)

// dynamic smem layout (floats): Zs[256][128] | Es[16][132] | Rv[128][16] | Ri[128][16]
#define SM_ZS    0
#define SM_ES    (DDIM * QT)                    // 32768
#define SM_RV    (SM_ES + DK * ES_STRIDE)       // 34880
#define SM_RI    (SM_RV + QT * 16)              // 36928
#define SM_FLOATS (SM_RI + QT * 16)             // 38976
#define SMEM_BYTES (SM_FLOATS * 4)              // 155904

__device__ float  g_ehn[N_EMB];
__device__ float  g_pval[NSPLIT * NQ];
__device__ int    g_pidx[NSPLIT * NQ];
__device__ int    g_idx[NQ];
__device__ double g_diff;

__device__ __forceinline__ unsigned long long pack2(float x) {
    unsigned long long r;
    asm("mov.b64 %0, {%1, %1};" : "=l"(r) : "r"(__float_as_uint(x)));
    return r;
}
#define FFMA2(acc, a, b) \
    asm("fma.rn.f32x2 %0, %1, %2, %0;" : "+l"(acc) : "l"(a), "l"(b))

// ---------------------------------------------------------------------------
// k_prep: 0.5*||e_k||^2 for all codes; zero the diff accumulator.
// grid 1024, block 256 (one warp per embedding row, 8 rows/block)
// ---------------------------------------------------------------------------
__global__ void k_prep(const float* __restrict__ emb) {
    if (blockIdx.x == 0 && threadIdx.x == 0) g_diff = 0.0;
    int row  = blockIdx.x * 8 + (threadIdx.x >> 5);
    int lane = threadIdx.x & 31;
    const float4* e4 = (const float4*)(emb + (size_t)row * DDIM);
    float s = 0.f;
    for (int i = lane; i < DDIM / 4; i += 32) {
        float4 v = e4[i];
        s += v.x * v.x + v.y * v.y + v.z * v.z + v.w * v.w;
    }
#pragma unroll
    for (int o = 16; o; o >>= 1) s += __shfl_xor_sync(0xffffffffu, s, o);
    if (lane == 0) g_ehn[row] = 0.5f * s;
}

// ---------------------------------------------------------------------------
// k_argmin: tiled score GEMM + running argmin.
// grid (NQ/QT, NSPLIT), block 256 (16x16 layout, 8q x 8e per thread)
// score_k = 0.5||e_k||^2 - z.e_k   (argmin == reference argmin)
// ---------------------------------------------------------------------------
__global__ void __launch_bounds__(256, 1)
k_argmin(const float* __restrict__ z, const float* __restrict__ emb) {
    extern __shared__ float sm[];
    float* Zs = sm + SM_ZS;
    float* Es = sm + SM_ES;
    float* Rv = sm + SM_RV;
    int*   Ri = (int*)(sm + SM_RI);

    const int tid = threadIdx.x;
    const int tx  = tid & 15;     // embedding cols
    const int ty  = tid >> 4;     // query rows
    const int qt  = blockIdx.x;
    const int sp  = blockIdx.y;
    const int qbase = qt * QT;
    const int b  = qbase / HW;
    const int nb = qbase % HW;
    const float* zb = z + (size_t)b * DDIM * HW + nb;

    // Stage the full 128x256 query tile: Zs[d][q] (q contiguous -> coalesced)
    {
        const int q0 = (tid & 31) * 4;
        for (int d = tid >> 5; d < DDIM; d += 8) {
            float4 v = *(const float4*)(zb + (size_t)d * HW + q0);
            *(float4*)(Zs + d * QT + q0) = v;
        }
    }
    __syncthreads();

    float bv[8];
    int   bi[8];
#pragma unroll
    for (int i = 0; i < 8; i++) { bv[i] = 3.4e38f; bi[i] = 0; }

    const int kbase = sp * KSPLIT;
    for (int et = 0; et < KSPLIT; et += ET) {
        const int e0 = kbase + et;

        unsigned long long acc[8][4];
#pragma unroll
        for (int i = 0; i < 8; i++)
#pragma unroll
            for (int jp = 0; jp < 4; jp++) acc[i][jp] = 0ull;

        float ehnv[8];
#pragma unroll
        for (int j = 0; j < 8; j++) ehnv[j] = g_ehn[e0 + tx * 8 + j];

        for (int dc = 0; dc < DDIM; dc += DK) {
            // Es[kk][e] = emb[e0+e][dc+kk], kk<16
            {
                const int e  = tid >> 1;
                const int k8 = (tid & 1) * 8;
                const float* src = emb + (size_t)(e0 + e) * DDIM + dc + k8;
                float4 a0 = *(const float4*)(src);
                float4 a1 = *(const float4*)(src + 4);
                Es[(k8 + 0) * ES_STRIDE + e] = a0.x;
                Es[(k8 + 1) * ES_STRIDE + e] = a0.y;
                Es[(k8 + 2) * ES_STRIDE + e] = a0.z;
                Es[(k8 + 3) * ES_STRIDE + e] = a0.w;
                Es[(k8 + 4) * ES_STRIDE + e] = a1.x;
                Es[(k8 + 5) * ES_STRIDE + e] = a1.y;
                Es[(k8 + 6) * ES_STRIDE + e] = a1.z;
                Es[(k8 + 7) * ES_STRIDE + e] = a1.w;
            }
            __syncthreads();
#pragma unroll
            for (int kk = 0; kk < DK; kk++) {
                const float* zr = Zs + (dc + kk) * QT + ty * 8;
                float4 z0 = *(const float4*)zr;
                float4 z1 = *(const float4*)(zr + 4);
                unsigned long long zz[8];
                zz[0] = pack2(z0.x); zz[1] = pack2(z0.y);
                zz[2] = pack2(z0.z); zz[3] = pack2(z0.w);
                zz[4] = pack2(z1.x); zz[5] = pack2(z1.y);
                zz[6] = pack2(z1.z); zz[7] = pack2(z1.w);
                const ulonglong2* er =
                    (const ulonglong2*)(Es + kk * ES_STRIDE + tx * 8);
                ulonglong2 ea = er[0], eb = er[1];
                unsigned long long ee[4] = {ea.x, ea.y, eb.x, eb.y};
#pragma unroll
                for (int i = 0; i < 8; i++) {
                    FFMA2(acc[i][0], zz[i], ee[0]);
                    FFMA2(acc[i][1], zz[i], ee[1]);
                    FFMA2(acc[i][2], zz[i], ee[2]);
                    FFMA2(acc[i][3], zz[i], ee[3]);
                }
            }
            __syncthreads();
        }

        // epilogue: score = 0.5||e||^2 - dot; running argmin (ascending e ->
        // strict '<' keeps the lowest index on ties, matching argmin order)
#pragma unroll
        for (int i = 0; i < 8; i++) {
#pragma unroll
            for (int jp = 0; jp < 4; jp++) {
                float lo = __uint_as_float((unsigned)(acc[i][jp] & 0xffffffffull));
                float hi = __uint_as_float((unsigned)(acc[i][jp] >> 32));
                int j0 = 2 * jp;
                float v0 = ehnv[j0] - lo;
                if (v0 < bv[i]) { bv[i] = v0; bi[i] = e0 + tx * 8 + j0; }
                float v1 = ehnv[j0 + 1] - hi;
                if (v1 < bv[i]) { bv[i] = v1; bi[i] = e0 + tx * 8 + j0 + 1; }
            }
        }
    }

    // cross-tx reduction (tx ascending == e ascending within a tile)
#pragma unroll
    for (int i = 0; i < 8; i++) {
        int q = ty * 8 + i;
        Rv[q * 16 + tx] = bv[i];
        Ri[q * 16 + tx] = bi[i];
    }
    __syncthreads();
    if (tid < QT) {
        float best = Rv[tid * 16];
        int   bidx = Ri[tid * 16];
#pragma unroll
        for (int t = 1; t < 16; t++) {
            float v = Rv[tid * 16 + t];
            if (v < best) { best = v; bidx = Ri[tid * 16 + t]; }
        }
        g_pval[sp * NQ + qbase + tid] = best;
        g_pidx[sp * NQ + qbase + tid] = bidx;
    }
}

// ---------------------------------------------------------------------------
// k_reduce: merge split-K partials (ascending split == ascending k)
// ---------------------------------------------------------------------------
__global__ void k_reduce(float* __restrict__ out) {
    int n = blockIdx.x * 256 + threadIdx.x;
    float best = g_pval[n];
    int   bidx = g_pidx[n];
#pragma unroll
    for (int s = 1; s < NSPLIT; s++) {
        float v = g_pval[s * NQ + n];
        if (v < best) { best = v; bidx = g_pidx[s * NQ + n]; }
    }
    g_idx[n] = bidx;
    out[ZQ_ELEMS + 1 + n] = (float)bidx;
}

// ---------------------------------------------------------------------------
// k_scatter: z_q[b][c][h][w] = emb[idx[n]][c] via smem transpose; diff partials
// grid 1024 (= b*32 + h), block 256
// ---------------------------------------------------------------------------
__global__ void k_scatter(const float* __restrict__ z,
                          const float* __restrict__ emb,
                          float* __restrict__ out) {
    __shared__ float Ts[32][257];
    __shared__ int   sidx[32];
    __shared__ float spart[8];
    const int bh = blockIdx.x;
    const int b  = bh >> 5;
    const int h  = bh & 31;
    const int t  = threadIdx.x;

    if (t < 32) sidx[t] = g_idx[b * HW + h * 32 + t];
    __syncthreads();
    {
        const int wr = t >> 3;
        const int c0 = (t & 7) * 32;
        const float* er = emb + (size_t)sidx[wr] * DDIM + c0;
        for (int c = 0; c < 32; c += 4) {
            float4 v = *(const float4*)(er + c);
            Ts[wr][c0 + c + 0] = v.x;
            Ts[wr][c0 + c + 1] = v.y;
            Ts[wr][c0 + c + 2] = v.z;
            Ts[wr][c0 + c + 3] = v.w;
        }
    }
    __syncthreads();

    float ds = 0.f;
    const int w  = t & 31;
    const int cg = t >> 5;
    const size_t basebh = (size_t)b * DDIM * HW + (size_t)h * 32;
    for (int c = cg; c < DDIM; c += 8) {
        float v = Ts[w][c];
        size_t g = basebh + (size_t)c * HW + w;
        float zv = z[g];
        out[g] = v;
        float df = v - zv;
        ds += df * df;
    }
#pragma unroll
    for (int o = 16; o; o >>= 1) ds += __shfl_xor_sync(0xffffffffu, ds, o);
    if ((t & 31) == 0) spart[t >> 5] = ds;
    __syncthreads();
    if (t == 0) {
        float s = 0.f;
#pragma unroll
        for (int i = 0; i < 8; i++) s += spart[i];
        atomicAdd(&g_diff, (double)s);
    }
}

__global__ void k_final(float* __restrict__ out) {
    out[ZQ_ELEMS] = (float)(0.25 * g_diff / (double)ZQ_ELEMS);
}

// ---------------------------------------------------------------------------
extern "C" void kernel_launch(void* const* d_in, const int* in_sizes, int n_in,
                              void* d_out, int out_size) {
    const float* z   = (const float*)d_in[0];
    const float* emb = (const float*)d_in[1];
    float* out = (float*)d_out;

    cudaFuncSetAttribute(k_argmin,
                         cudaFuncAttributeMaxDynamicSharedMemorySize,
                         SMEM_BYTES);

    k_prep<<<N_EMB / 8, 256>>>(emb);
    dim3 g(NQ / QT, NSPLIT);
    k_argmin<<<g, 256, SMEM_BYTES>>>(z, emb);
    k_reduce<<<NQ / 256, 256>>>(out);
    k_scatter<<<BB * HH, 256>>>(z, emb, out);
    k_final<<<1, 1>>>(out);
}